// round 16
// baseline (speedup 1.0000x reference)
#include <cuda_runtime.h>
#include <cuda_bf16.h>
#include <cstdint>

#define N 4096
#define DF 64

// Scratch (allocation-free rule: __device__ globals)
__device__ float g_D[(size_t)N * N];   // 64 MB distance matrix, diagonal = +inf
__device__ float g_sq[N];              // squared norms

__device__ __forceinline__ float finf() { return __int_as_float(0x7f800000); }

// ---------------------------------------------------------------------------
// Kernel 0: squared norms
// ---------------------------------------------------------------------------
__global__ void sq_kernel(const float* __restrict__ x) {
    int i = blockIdx.x * blockDim.x + threadIdx.x;
    if (i >= N) return;
    const float4* xi = (const float4*)(x + (size_t)i * DF);
    float s = 0.f;
#pragma unroll
    for (int k = 0; k < DF / 4; k++) {
        float4 v = xi[k];
        s += v.x * v.x + v.y * v.y + v.z * v.z + v.w * v.w;
    }
    g_sq[i] = s;
}

// ---------------------------------------------------------------------------
// Kernel 1: distance matrix, 64x64 tiles, 256 threads, 4x4 per thread.
// (UNCHANGED — D must stay bit-identical: changing fp32 accumulation order
// perturbs D at the ulp level and risks a Prim trajectory flip.)
// ---------------------------------------------------------------------------
__global__ __launch_bounds__(256) void dist_kernel(const float* __restrict__ x) {
    __shared__ __align__(16) float sA[DF * 68];
    __shared__ __align__(16) float sB[DF * 68];

    const int t    = threadIdx.x;
    const int lrow = t >> 2;      // 0..63
    const int q    = t & 3;       // 0..3
    const int i0   = blockIdx.y * 64;
    const int j0   = blockIdx.x * 64;

    {
        const float4* xa = (const float4*)(x + (size_t)(i0 + lrow) * DF) + q * 4;
        const float4* xb = (const float4*)(x + (size_t)(j0 + lrow) * DF) + q * 4;
#pragma unroll
        for (int u = 0; u < 4; u++) {
            float4 va = xa[u];
            float4 vb = xb[u];
            int k0 = q * 16 + u * 4;
            sA[(k0 + 0) * 68 + lrow] = va.x;
            sA[(k0 + 1) * 68 + lrow] = va.y;
            sA[(k0 + 2) * 68 + lrow] = va.z;
            sA[(k0 + 3) * 68 + lrow] = va.w;
            sB[(k0 + 0) * 68 + lrow] = vb.x;
            sB[(k0 + 1) * 68 + lrow] = vb.y;
            sB[(k0 + 2) * 68 + lrow] = vb.z;
            sB[(k0 + 3) * 68 + lrow] = vb.w;
        }
    }
    __syncthreads();

    const int tx = t & 15;
    const int ty = t >> 4;

    float acc[4][4];
#pragma unroll
    for (int r = 0; r < 4; r++)
#pragma unroll
        for (int c = 0; c < 4; c++) acc[r][c] = 0.f;

#pragma unroll 8
    for (int k = 0; k < DF; k++) {
        float4 a = *(const float4*)&sA[k * 68 + ty * 4];
        float4 b = *(const float4*)&sB[k * 68 + tx * 4];
        float av[4] = {a.x, a.y, a.z, a.w};
        float bv[4] = {b.x, b.y, b.z, b.w};
#pragma unroll
        for (int r = 0; r < 4; r++)
#pragma unroll
            for (int c = 0; c < 4; c++) acc[r][c] = fmaf(av[r], bv[c], acc[r][c]);
    }

    float sqI[4], sqJ[4];
#pragma unroll
    for (int r = 0; r < 4; r++) sqI[r] = g_sq[i0 + ty * 4 + r];
#pragma unroll
    for (int c = 0; c < 4; c++) sqJ[c] = g_sq[j0 + tx * 4 + c];

#pragma unroll
    for (int r = 0; r < 4; r++) {
        int gi = i0 + ty * 4 + r;
        float4 o;
        float ov[4];
#pragma unroll
        for (int c = 0; c < 4; c++) {
            int gj = j0 + tx * 4 + c;
            float d2 = sqI[r] + sqJ[c] - 2.f * acc[r][c];
            float d  = sqrtf(fmaxf(d2, 1e-12f));
            ov[c] = (gi == gj) ? finf() : d;
        }
        o.x = ov[0]; o.y = ov[1]; o.z = ov[2]; o.w = ov[3];
        *(float4*)(g_D + (size_t)gi * N + j0 + tx * 4) = o;
    }
}

// ---------------------------------------------------------------------------
// Kernel 2: Prim scan — the proven R5 core, verbatim, plus ONE exact micro:
// stage-2 reads s_warp[par][lane & 7] in ALL lanes (4-way replicated keys;
// min over duplicates is unchanged, and index candidates replicate equally
// so the index REDUX result is identical) — deletes a SETP+SEL from the
// critical tail and makes the LDS a conflict-free broadcast.
//
// Selection semantics (bit-exact jnp.argmin): min on exact fp32 bits under
// unsigned compare (sentinel -1.0f sorts after +inf, absorbing under fminf),
// strict-< tree keeps the earliest index, two REDUX per stage with
// lowest-global-index tiebreak.
// ---------------------------------------------------------------------------
__global__ __launch_bounds__(256, 1) void prim_kernel(float* __restrict__ out) {
    __shared__ unsigned long long s_warp[2][8];

    const int tid  = threadIdx.x;
    const int lane = tid & 31;
    const int wid  = tid >> 5;
    const int base = wid * 512 + lane * 4;   // global idx of e=0

    float m[16];
#pragma unroll
    for (int e = 0; e < 16; e++) m[e] = finf();
    if (tid == 0) m[0] = -1.0f;   // vertex 0 starts in the tree

    int j   = 0;
    int par = 0;

    for (int step = 0; step < N - 1; step++) {
        // ---- row loads first (MLP=4); everything else overlaps them
        const float4* rp = (const float4*)(g_D + ((size_t)j << 12)) + wid * 128 + lane;
        float4 q0 = __ldcg(rp);
        float4 q1 = __ldcg(rp + 32);
        float4 q2 = __ldcg(rp + 64);
        float4 q3 = __ldcg(rp + 96);
        float dv[16] = {q0.x, q0.y, q0.z, q0.w, q1.x, q1.y, q1.z, q1.w,
                        q2.x, q2.y, q2.z, q2.w, q3.x, q3.y, q3.z, q3.w};

        // ---- merge + implicit mask (sentinel bits sort after +inf)
        unsigned v[16];
#pragma unroll
        for (int e = 0; e < 16; e++) {
            m[e] = fminf(m[e], dv[e]);
            v[e] = __float_as_uint(m[e]);
        }

        // ---- local argmin tree (strict < keeps earlier index)
        unsigned bv[8]; int be[8];
#pragma unroll
        for (int k = 0; k < 8; k++) {
            bool p = v[2 * k + 1] < v[2 * k];
            bv[k] = p ? v[2 * k + 1] : v[2 * k];
            be[k] = p ? (2 * k + 1) : (2 * k);
        }
#pragma unroll
        for (int k = 0; k < 4; k++) {
            bool p = bv[2 * k + 1] < bv[2 * k];
            bv[k] = p ? bv[2 * k + 1] : bv[2 * k];
            be[k] = p ? be[2 * k + 1] : be[2 * k];
        }
#pragma unroll
        for (int k = 0; k < 2; k++) {
            bool p = bv[2 * k + 1] < bv[2 * k];
            bv[k] = p ? bv[2 * k + 1] : bv[2 * k];
            be[k] = p ? be[2 * k + 1] : be[2 * k];
        }
        bool p0 = bv[1] < bv[0];
        unsigned myv = p0 ? bv[1] : bv[0];
        int      e0  = p0 ? be[1] : be[0];
        int besti = base + ((e0 >> 2) << 7) + (e0 & 3);

        // ---- stage 1: warp argmin via two REDUX ops (exact)
        unsigned wmin = __reduce_min_sync(0xffffffffu, myv);
        unsigned cand = (myv == wmin) ? (unsigned)besti : 0xffffffffu;
        unsigned widx = __reduce_min_sync(0xffffffffu, cand);
        if (lane == 0)
            s_warp[par][wid] = ((unsigned long long)wmin << 32) | widx;
        __syncthreads();

        // ---- stage 2: all lanes read a replicated key (4-way broadcast LDS,
        //      no predicate/SEL); min over duplicates is identical
        unsigned long long k8 = s_warp[par][lane & 7];
        unsigned kv   = (unsigned)(k8 >> 32);
        unsigned gmin = __reduce_min_sync(0xffffffffu, kv);
        unsigned c2   = (kv == gmin) ? (unsigned)k8 : 0xffffffffu;
        unsigned gi   = __reduce_min_sync(0xffffffffu, c2);

        j = (int)gi;
        int own = (int)(((gi >> 9) << 5) | ((gi >> 2) & 31));
        if (own == tid) {
            int e = (int)(((gi >> 5) & 0xCu) | (gi & 3u));
            m[e] = -1.0f;   // sentinel (survives fminf, sorts last)
        }
        if (tid == 0)
            *(float2*)(out + 2 * step) = make_float2(0.0f, __uint_as_float(gmin));
        par ^= 1;
    }
}

// ---------------------------------------------------------------------------
extern "C" void kernel_launch(void* const* d_in, const int* in_sizes, int n_in,
                              void* d_out, int out_size) {
    const float* x   = (const float*)d_in[0];
    float*       out = (float*)d_out;

    sq_kernel<<<(N + 255) / 256, 256>>>(x);
    dim3 grid(N / 64, N / 64);
    dist_kernel<<<grid, 256>>>(x);
    prim_kernel<<<1, 256>>>(out);
}

// round 17
// speedup vs baseline: 1.3812x; 1.3812x over previous
#include <cuda_runtime.h>
#include <cuda_bf16.h>
#include <cstdint>

#define N 4096
#define DF 64

// Scratch (allocation-free rule: __device__ globals)
__device__ float g_D[(size_t)N * N];   // 64 MB distance matrix, diagonal = +inf
__device__ float g_sq[N];              // squared norms

__device__ __forceinline__ float finf() { return __int_as_float(0x7f800000); }

// ---------------------------------------------------------------------------
// Kernel 0: squared norms
// ---------------------------------------------------------------------------
__global__ void sq_kernel(const float* __restrict__ x) {
    int i = blockIdx.x * blockDim.x + threadIdx.x;
    if (i >= N) return;
    const float4* xi = (const float4*)(x + (size_t)i * DF);
    float s = 0.f;
#pragma unroll
    for (int k = 0; k < DF / 4; k++) {
        float4 v = xi[k];
        s += v.x * v.x + v.y * v.y + v.z * v.z + v.w * v.w;
    }
    g_sq[i] = s;
}

// ---------------------------------------------------------------------------
// Kernel 1: distance matrix, 64x64 tiles, 256 threads, 4x4 per thread.
// (UNCHANGED — D must stay bit-identical: changing fp32 accumulation order
// perturbs D at the ulp level and risks a Prim trajectory flip.)
// ---------------------------------------------------------------------------
__global__ __launch_bounds__(256) void dist_kernel(const float* __restrict__ x) {
    __shared__ __align__(16) float sA[DF * 68];
    __shared__ __align__(16) float sB[DF * 68];

    const int t    = threadIdx.x;
    const int lrow = t >> 2;      // 0..63
    const int q    = t & 3;       // 0..3
    const int i0   = blockIdx.y * 64;
    const int j0   = blockIdx.x * 64;

    {
        const float4* xa = (const float4*)(x + (size_t)(i0 + lrow) * DF) + q * 4;
        const float4* xb = (const float4*)(x + (size_t)(j0 + lrow) * DF) + q * 4;
#pragma unroll
        for (int u = 0; u < 4; u++) {
            float4 va = xa[u];
            float4 vb = xb[u];
            int k0 = q * 16 + u * 4;
            sA[(k0 + 0) * 68 + lrow] = va.x;
            sA[(k0 + 1) * 68 + lrow] = va.y;
            sA[(k0 + 2) * 68 + lrow] = va.z;
            sA[(k0 + 3) * 68 + lrow] = va.w;
            sB[(k0 + 0) * 68 + lrow] = vb.x;
            sB[(k0 + 1) * 68 + lrow] = vb.y;
            sB[(k0 + 2) * 68 + lrow] = vb.z;
            sB[(k0 + 3) * 68 + lrow] = vb.w;
        }
    }
    __syncthreads();

    const int tx = t & 15;
    const int ty = t >> 4;

    float acc[4][4];
#pragma unroll
    for (int r = 0; r < 4; r++)
#pragma unroll
        for (int c = 0; c < 4; c++) acc[r][c] = 0.f;

#pragma unroll 8
    for (int k = 0; k < DF; k++) {
        float4 a = *(const float4*)&sA[k * 68 + ty * 4];
        float4 b = *(const float4*)&sB[k * 68 + tx * 4];
        float av[4] = {a.x, a.y, a.z, a.w};
        float bv[4] = {b.x, b.y, b.z, b.w};
#pragma unroll
        for (int r = 0; r < 4; r++)
#pragma unroll
            for (int c = 0; c < 4; c++) acc[r][c] = fmaf(av[r], bv[c], acc[r][c]);
    }

    float sqI[4], sqJ[4];
#pragma unroll
    for (int r = 0; r < 4; r++) sqI[r] = g_sq[i0 + ty * 4 + r];
#pragma unroll
    for (int c = 0; c < 4; c++) sqJ[c] = g_sq[j0 + tx * 4 + c];

#pragma unroll
    for (int r = 0; r < 4; r++) {
        int gi = i0 + ty * 4 + r;
        float4 o;
        float ov[4];
#pragma unroll
        for (int c = 0; c < 4; c++) {
            int gj = j0 + tx * 4 + c;
            float d2 = sqI[r] + sqJ[c] - 2.f * acc[r][c];
            float d  = sqrtf(fmaxf(d2, 1e-12f));
            ov[c] = (gi == gj) ? finf() : d;
        }
        o.x = ov[0]; o.y = ov[1]; o.z = ov[2]; o.w = ov[3];
        *(float4*)(g_D + (size_t)gi * N + j0 + tx * 4) = o;
    }
}

// ---------------------------------------------------------------------------
// Kernel 2: Prim scan — converged optimum of the single-SM serial shape.
// 256 threads / 8 warps, 16 elems/thread in registers; sentinel -1.0f is
// absorbing under fminf AND sorts after +inf under unsigned compare (dual
// ordering => zero masking instructions); strict-< tree keeps the earliest
// index; two REDUX per stage with lowest-global-index tiebreak => bit-exact
// jnp.argmin semantics. Stage-2 reads a 4-way replicated key (broadcast
// LDS.64, no predicate) — min over duplicates is identical.
// ---------------------------------------------------------------------------
__global__ __launch_bounds__(256, 1) void prim_kernel(float* __restrict__ out) {
    __shared__ unsigned long long s_warp[2][8];

    const int tid  = threadIdx.x;
    const int lane = tid & 31;
    const int wid  = tid >> 5;
    const int base = wid * 512 + lane * 4;   // global idx of e=0

    float m[16];
#pragma unroll
    for (int e = 0; e < 16; e++) m[e] = finf();
    if (tid == 0) m[0] = -1.0f;   // vertex 0 starts in the tree

    int j   = 0;
    int par = 0;

    for (int step = 0; step < N - 1; step++) {
        // ---- row loads first (MLP=4); everything else overlaps them
        const float4* rp = (const float4*)(g_D + ((size_t)j << 12)) + wid * 128 + lane;
        float4 q0 = __ldcg(rp);
        float4 q1 = __ldcg(rp + 32);
        float4 q2 = __ldcg(rp + 64);
        float4 q3 = __ldcg(rp + 96);
        float dv[16] = {q0.x, q0.y, q0.z, q0.w, q1.x, q1.y, q1.z, q1.w,
                        q2.x, q2.y, q2.z, q2.w, q3.x, q3.y, q3.z, q3.w};

        // ---- merge + implicit mask (sentinel bits sort after +inf)
        unsigned v[16];
#pragma unroll
        for (int e = 0; e < 16; e++) {
            m[e] = fminf(m[e], dv[e]);
            v[e] = __float_as_uint(m[e]);
        }

        // ---- local argmin tree (strict < keeps earlier index)
        unsigned bv[8]; int be[8];
#pragma unroll
        for (int k = 0; k < 8; k++) {
            bool p = v[2 * k + 1] < v[2 * k];
            bv[k] = p ? v[2 * k + 1] : v[2 * k];
            be[k] = p ? (2 * k + 1) : (2 * k);
        }
#pragma unroll
        for (int k = 0; k < 4; k++) {
            bool p = bv[2 * k + 1] < bv[2 * k];
            bv[k] = p ? bv[2 * k + 1] : bv[2 * k];
            be[k] = p ? be[2 * k + 1] : be[2 * k];
        }
#pragma unroll
        for (int k = 0; k < 2; k++) {
            bool p = bv[2 * k + 1] < bv[2 * k];
            bv[k] = p ? bv[2 * k + 1] : bv[2 * k];
            be[k] = p ? be[2 * k + 1] : be[2 * k];
        }
        bool p0 = bv[1] < bv[0];
        unsigned myv = p0 ? bv[1] : bv[0];
        int      e0  = p0 ? be[1] : be[0];
        int besti = base + ((e0 >> 2) << 7) + (e0 & 3);

        // ---- stage 1: warp argmin via two REDUX ops (exact)
        unsigned wmin = __reduce_min_sync(0xffffffffu, myv);
        unsigned cand = (myv == wmin) ? (unsigned)besti : 0xffffffffu;
        unsigned widx = __reduce_min_sync(0xffffffffu, cand);
        if (lane == 0)
            s_warp[par][wid] = ((unsigned long long)wmin << 32) | widx;
        __syncthreads();

        // ---- stage 2: all lanes read a replicated key (broadcast LDS.64);
        //      min over duplicates is identical
        unsigned long long k8 = s_warp[par][lane & 7];
        unsigned kv   = (unsigned)(k8 >> 32);
        unsigned gmin = __reduce_min_sync(0xffffffffu, kv);
        unsigned c2   = (kv == gmin) ? (unsigned)k8 : 0xffffffffu;
        unsigned gi   = __reduce_min_sync(0xffffffffu, c2);

        j = (int)gi;
        int own = (int)(((gi >> 9) << 5) | ((gi >> 2) & 31));
        if (own == tid) {
            int e = (int)(((gi >> 5) & 0xCu) | (gi & 3u));
            m[e] = -1.0f;   // sentinel (survives fminf, sorts last)
        }
        if (tid == 0)
            *(float2*)(out + 2 * step) = make_float2(0.0f, __uint_as_float(gmin));
        par ^= 1;
    }
}

// ---------------------------------------------------------------------------
extern "C" void kernel_launch(void* const* d_in, const int* in_sizes, int n_in,
                              void* d_out, int out_size) {
    const float* x   = (const float*)d_in[0];
    float*       out = (float*)d_out;

    sq_kernel<<<(N + 255) / 256, 256>>>(x);
    dim3 grid(N / 64, N / 64);
    dist_kernel<<<grid, 256>>>(x);
    prim_kernel<<<1, 256>>>(out);
}